// round 1
// baseline (speedup 1.0000x reference)
#include <cuda_runtime.h>

#define NN 100000
#define NE 1600000
#define NG 512

// Scratch (device globals; no allocation allowed)
__device__ float g_xcat1[NN * 128];   // [x(32) | agg0 | agg1 | agg2]  per node
__device__ float g_xcat2[NN * 256];   // [x1(64) | agg0 | agg1 | agg2] per node
__device__ float g_cnt[3 * NN];       // per-(rel,dst) edge counts
__device__ float g_pool[NG * 64];     // per-graph feature sums
__device__ float g_pcnt[NG];          // per-graph node counts

static __device__ __forceinline__ void red_add_v4(float* p, float4 v) {
    asm volatile("red.global.add.v4.f32 [%0], {%1,%2,%3,%4};"
                 :: "l"(p), "f"(v.x), "f"(v.y), "f"(v.z), "f"(v.w) : "memory");
}

// ---------------------------------------------------------------------------
// Zero all scratch buffers (grid-stride, float4)
// ---------------------------------------------------------------------------
__global__ void zero_all_kernel() {
    const float4 z = {0.f, 0.f, 0.f, 0.f};
    int stride = gridDim.x * blockDim.x;
    int i0 = blockIdx.x * blockDim.x + threadIdx.x;
    int n;
    n = NN * 128 / 4; for (int i = i0; i < n; i += stride) ((float4*)g_xcat1)[i] = z;
    n = NN * 256 / 4; for (int i = i0; i < n; i += stride) ((float4*)g_xcat2)[i] = z;
    n = 3 * NN / 4;   for (int i = i0; i < n; i += stride) ((float4*)g_cnt)[i]   = z;
    n = NG * 64 / 4;  for (int i = i0; i < n; i += stride) ((float4*)g_pool)[i]  = z;
    n = NG / 4;       for (int i = i0; i < n; i += stride) ((float4*)g_pcnt)[i]  = z;
}

// ---------------------------------------------------------------------------
// Embedding + pre-MLP: x32 = relu(concat(shape_emb[s], color_emb[c]) @ pre_w + pre_b)
// thread = (node, out_col)
// ---------------------------------------------------------------------------
__global__ void embed_kernel(const int* __restrict__ nf,
                             const float* __restrict__ se,
                             const float* __restrict__ ce,
                             const float* __restrict__ pw,
                             const float* __restrict__ pb) {
    int idx = blockIdx.x * blockDim.x + threadIdx.x;
    if (idx >= NN * 32) return;
    int i = idx >> 5, c = idx & 31;
    int s = nf[2 * i], col = nf[2 * i + 1];
    float acc = pb[c];
#pragma unroll
    for (int k = 0; k < 8; k++) acc = fmaf(se[s * 8 + k], pw[k * 32 + c], acc);
#pragma unroll
    for (int k = 0; k < 8; k++) acc = fmaf(ce[col * 8 + k], pw[(8 + k) * 32 + c], acc);
    g_xcat1[(size_t)i * 128 + c] = fmaxf(acc, 0.f);
}

// ---------------------------------------------------------------------------
// Edge scatter: agg[rel][dst] += x[src] (vectorized reductions, C/4 threads/edge)
// LAYER 1: C=32 (x in g_xcat1 seg0), also accumulates per-(rel,dst) counts.
// LAYER 2: C=64 (x1 in g_xcat2 seg0).
// ---------------------------------------------------------------------------
template <int LAYER>
__global__ void scatter_kernel(const int* __restrict__ ei,
                               const int* __restrict__ et) {
    constexpr int C = (LAYER == 1) ? 32 : 64;
    constexpr int K = (LAYER == 1) ? 128 : 256;
    constexpr int SH = (LAYER == 1) ? 3 : 4;        // log2(C/4)
    constexpr int GM = (1 << SH) - 1;
    float* X = (LAYER == 1) ? g_xcat1 : g_xcat2;

    int idx = blockIdx.x * blockDim.x + threadIdx.x;
    if (idx >= NE * (C / 4)) return;
    int e = idx >> SH;
    int g = idx & GM;
    int src = ei[e];
    int dst = ei[NE + e];
    int t = et[e];
    float4 v = *(const float4*)(X + (size_t)src * K + g * 4);
    red_add_v4(X + (size_t)dst * K + C + t * C + g * 4, v);
    if (LAYER == 1 && g == 0) atomicAdd(&g_cnt[t * NN + dst], 1.0f);
}

// ---------------------------------------------------------------------------
// Normalize aggregates in place: agg_r /= max(cnt_r, 1)
// ---------------------------------------------------------------------------
template <int LAYER>
__global__ void norm_kernel() {
    constexpr int C = (LAYER == 1) ? 32 : 64;
    constexpr int K = (LAYER == 1) ? 128 : 256;
    constexpr int J4 = 3 * C / 4;                    // float4 groups per node
    float* X = (LAYER == 1) ? g_xcat1 : g_xcat2;

    int idx = blockIdx.x * blockDim.x + threadIdx.x;
    if (idx >= NN * J4) return;
    int i = idx / J4;
    int j4 = idx - i * J4;
    int r = j4 / (C / 4);
    float c = g_cnt[r * NN + i];
    float inv = 1.0f / fmaxf(c, 1.0f);
    float4* p = (float4*)(X + (size_t)i * K + C) + j4;
    float4 v = *p;
    v.x *= inv; v.y *= inv; v.z *= inv; v.w *= inv;
    *p = v;
}

// ---------------------------------------------------------------------------
// Dense GEMM: out[node] = relu(xcat[node] @ [root; rel] + bias)
// Tile: 64 nodes x 64 cols per block, 256 threads, 4x4 register blocking,
// K-chunks of 64, static smem (32KB).
// LAYER 1 epilogue: write x1 into g_xcat2 seg0.
// LAYER 2 epilogue: vector-reduce into per-graph pool sums.
// ---------------------------------------------------------------------------
template <int LAYER>
__global__ __launch_bounds__(256) void gemm_kernel(const float* __restrict__ root,
                                                   const float* __restrict__ rel,
                                                   const float* __restrict__ bias,
                                                   const int* __restrict__ batch) {
    constexpr int K = (LAYER == 1) ? 128 : 256;
    constexpr int C = (LAYER == 1) ? 32 : 64;
    const float* X = (LAYER == 1) ? g_xcat1 : g_xcat2;

    __shared__ float s_x[64 * 64];     // [row][k]
    __shared__ float4 s_w[64 * 16];    // [k][col4]

    int n0 = blockIdx.x * 64;
    int cg = threadIdx.x & 15;         // col group (4 cols)
    int ng = threadIdx.x >> 4;         // node group (4 nodes)

    float acc[4][4] = {};

    for (int kc = 0; kc < K; kc += 64) {
        // Stage weights: rows kc..kc+63 of stacked [root; rel]
#pragma unroll
        for (int it = 0; it < 4; it++) {
            int idx = threadIdx.x + it * 256;
            int r = idx >> 4, c4 = idx & 15;
            int kr = kc + r;
            const float* wsrc = (kr < C) ? (root + (size_t)kr * 64)
                                         : (rel + (size_t)(kr - C) * 64);
            s_w[r * 16 + c4] = ((const float4*)wsrc)[c4];
        }
        // Stage X tile: 64 nodes x 64 k (clamped)
#pragma unroll
        for (int it = 0; it < 4; it++) {
            int idx = threadIdx.x + it * 256;
            int r = idx >> 4, c4 = idx & 15;
            int node = n0 + r; if (node >= NN) node = NN - 1;
            ((float4*)s_x)[r * 16 + c4] =
                *(const float4*)(X + (size_t)node * K + kc + c4 * 4);
        }
        __syncthreads();
#pragma unroll 16
        for (int k = 0; k < 64; k++) {
            float4 w = s_w[k * 16 + cg];
#pragma unroll
            for (int j = 0; j < 4; j++) {
                float xv = s_x[(ng * 4 + j) * 64 + k];
                acc[j][0] = fmaf(xv, w.x, acc[j][0]);
                acc[j][1] = fmaf(xv, w.y, acc[j][1]);
                acc[j][2] = fmaf(xv, w.z, acc[j][2]);
                acc[j][3] = fmaf(xv, w.w, acc[j][3]);
            }
        }
        __syncthreads();
    }

    float4 b = ((const float4*)bias)[cg];
#pragma unroll
    for (int j = 0; j < 4; j++) {
        int node = n0 + ng * 4 + j;
        if (node >= NN) continue;
        float4 v;
        v.x = fmaxf(acc[j][0] + b.x, 0.f);
        v.y = fmaxf(acc[j][1] + b.y, 0.f);
        v.z = fmaxf(acc[j][2] + b.z, 0.f);
        v.w = fmaxf(acc[j][3] + b.w, 0.f);
        if (LAYER == 1) {
            *(float4*)(g_xcat2 + (size_t)node * 256 + cg * 4) = v;
        } else {
            int g = batch[node];
            red_add_v4(&g_pool[g * 64 + cg * 4], v);
        }
    }
}

// ---------------------------------------------------------------------------
// Per-graph node counts
// ---------------------------------------------------------------------------
__global__ void pcnt_kernel(const int* __restrict__ batch) {
    int i = blockIdx.x * blockDim.x + threadIdx.x;
    if (i < NN) atomicAdd(&g_pcnt[batch[i]], 1.0f);
}

// ---------------------------------------------------------------------------
// Classifier: logits[g,c] = (pool[g]/cnt[g]) @ cls_w + cls_b
// ---------------------------------------------------------------------------
__global__ void cls_kernel(const float* __restrict__ cw,
                           const float* __restrict__ cb,
                           float* __restrict__ out) {
    int idx = blockIdx.x * blockDim.x + threadIdx.x;
    if (idx >= NG * 10) return;
    int g = idx / 10, c = idx - g * 10;
    float inv = 1.0f / fmaxf(g_pcnt[g], 1.0f);
    float acc = 0.f;
#pragma unroll
    for (int k = 0; k < 64; k++) acc = fmaf(g_pool[g * 64 + k], cw[k * 10 + c], acc);
    out[idx] = acc * inv + cb[c];
}

// ---------------------------------------------------------------------------
extern "C" void kernel_launch(void* const* d_in, const int* in_sizes, int n_in,
                              void* d_out, int out_size) {
    const int*   nf    = (const int*)d_in[0];    // node_feats [N,2]
    const int*   ei    = (const int*)d_in[1];    // edge_index [2,E]
    const int*   et    = (const int*)d_in[2];    // edge_type  [E]
    const int*   batch = (const int*)d_in[3];    // batch      [N]
    const float* se    = (const float*)d_in[4];  // shape_emb [16,8]
    const float* ce    = (const float*)d_in[5];  // color_emb [8,8]
    const float* pw    = (const float*)d_in[6];  // pre_w [16,32]
    const float* pb    = (const float*)d_in[7];  // pre_b [32]
    const float* root1 = (const float*)d_in[8];  // [32,64]
    const float* rel1  = (const float*)d_in[9];  // [3,32,64]
    const float* bias1 = (const float*)d_in[10]; // [64]
    const float* root2 = (const float*)d_in[11]; // [64,64]
    const float* rel2  = (const float*)d_in[12]; // [3,64,64]
    const float* bias2 = (const float*)d_in[13]; // [64]
    const float* cw    = (const float*)d_in[14]; // [64,10]
    const float* cb    = (const float*)d_in[15]; // [10]
    float* out = (float*)d_out;

    zero_all_kernel<<<1184, 256>>>();
    embed_kernel<<<(NN * 32 + 255) / 256, 256>>>(nf, se, ce, pw, pb);

    scatter_kernel<1><<<(NE * 8 + 255) / 256, 256>>>(ei, et);
    norm_kernel<1><<<(NN * 24 + 255) / 256, 256>>>();
    gemm_kernel<1><<<(NN + 63) / 64, 256>>>(root1, rel1, bias1, batch);

    scatter_kernel<2><<<(NE * 16 + 255) / 256, 256>>>(ei, et);
    norm_kernel<2><<<(NN * 48 + 255) / 256, 256>>>();
    gemm_kernel<2><<<(NN + 63) / 64, 256>>>(root2, rel2, bias2, batch);

    pcnt_kernel<<<(NN + 255) / 256, 256>>>(batch);
    cls_kernel<<<(NG * 10 + 255) / 256, 256>>>(cw, cb, out);
}

// round 2
// speedup vs baseline: 1.0788x; 1.0788x over previous
#include <cuda_runtime.h>

#define NN 100000
#define NE 1600000
#define NG 512

// ---------------------------------------------------------------------------
// Scratch (device globals; allocation is forbidden)
// ---------------------------------------------------------------------------
__device__ __align__(16) float g_x1[NN * 32];     // pre-MLP output      [NN,32]
__device__ __align__(16) float g_agg1[NN * 96];   // layer1 aggregates   [NN,3*32]
__device__ __align__(16) float g_x2[NN * 64];     // layer1 output       [NN,64]
__device__ __align__(16) float g_agg2[NN * 192];  // layer2 aggregates   [NN,3*64]
__device__ int   g_deg[NN];                       // in-degree per node
__device__ int   g_off[NN];                       // CSR offsets (exclusive scan)
__device__ int   g_part[128];                     // scan block partials
__device__ int   g_cursor[NN];                    // fill cursors
__device__ int   g_eidx[NE];                      // CSR payload: src | (rel<<17)
__device__ float g_pool[NG * 64];                 // per-graph sums

static __device__ __forceinline__ void red_add_v4(float* p, float4 v) {
    asm volatile("red.global.add.v4.f32 [%0], {%1,%2,%3,%4};"
                 :: "l"(p), "f"(v.x), "f"(v.y), "f"(v.z), "f"(v.w) : "memory");
}
static __device__ __forceinline__ void ffma2(unsigned long long& d,
                                             unsigned long long a,
                                             unsigned long long b) {
    asm("fma.rn.f32x2 %0, %1, %2, %0;" : "+l"(d) : "l"(a), "l"(b));
}

// ---------------------------------------------------------------------------
// init: zero deg/pool + embedding + pre-MLP  (x1 = relu(emb @ pre_w + pre_b))
// ---------------------------------------------------------------------------
__global__ void init_embed_kernel(const int* __restrict__ nf,
                                  const float* __restrict__ se,
                                  const float* __restrict__ ce,
                                  const float* __restrict__ pw,
                                  const float* __restrict__ pb) {
    int idx = blockIdx.x * blockDim.x + threadIdx.x;
    int stride = gridDim.x * blockDim.x;
    for (int i = idx; i < NN; i += stride) g_deg[i] = 0;
    for (int i = idx; i < NG * 64; i += stride) g_pool[i] = 0.f;
    if (idx < NN * 32) {
        int i = idx >> 5, c = idx & 31;
        int s = nf[2 * i], col = nf[2 * i + 1];
        float acc = pb[c];
#pragma unroll
        for (int k = 0; k < 8; k++) acc = fmaf(se[s * 8 + k], pw[k * 32 + c], acc);
#pragma unroll
        for (int k = 0; k < 8; k++) acc = fmaf(ce[col * 8 + k], pw[(8 + k) * 32 + c], acc);
        g_x1[(size_t)i * 32 + c] = fmaxf(acc, 0.f);
    }
}

// ---------------------------------------------------------------------------
// CSR build: histogram -> scan (2 kernels) -> fill
// ---------------------------------------------------------------------------
__global__ void hist_kernel(const int* __restrict__ ei) {
    int e = blockIdx.x * blockDim.x + threadIdx.x;
    if (e < NE) atomicAdd(&g_deg[ei[NE + e]], 1);
}

__global__ void scan_a_kernel() {
    __shared__ int s[1024];
    int i = blockIdx.x * 1024 + threadIdx.x;
    int v = (i < NN) ? g_deg[i] : 0;
    s[threadIdx.x] = v;
    __syncthreads();
    for (int ofs = 1; ofs < 1024; ofs <<= 1) {
        int t = (threadIdx.x >= ofs) ? s[threadIdx.x - ofs] : 0;
        __syncthreads();
        s[threadIdx.x] += t;
        __syncthreads();
    }
    if (i < NN) g_off[i] = s[threadIdx.x] - v;
    if (threadIdx.x == 1023) g_part[blockIdx.x] = s[1023];
}

__global__ void scan_b_kernel() {
    __shared__ int s[1024];
    int b = blockIdx.x;
    s[threadIdx.x] = (threadIdx.x < b) ? g_part[threadIdx.x] : 0;
    __syncthreads();
    for (int ofs = 512; ofs > 0; ofs >>= 1) {
        if (threadIdx.x < ofs) s[threadIdx.x] += s[threadIdx.x + ofs];
        __syncthreads();
    }
    int prefix = s[0];
    int i = b * 1024 + threadIdx.x;
    if (i < NN) {
        int o = g_off[i] + prefix;
        g_off[i] = o;
        g_cursor[i] = o;
    }
}

__global__ void fill_kernel(const int* __restrict__ ei,
                            const int* __restrict__ et) {
    int e = blockIdx.x * blockDim.x + threadIdx.x;
    if (e >= NE) return;
    int dst = ei[NE + e];
    int pos = atomicAdd(&g_cursor[dst], 1);
    g_eidx[pos] = ei[e] | (et[e] << 17);
}

// ---------------------------------------------------------------------------
// Gather aggregation: one warp per dst node; per-relation register accums;
// mean-normalize in place. Layer1: 32 cols (lane=col). Layer2: 64 cols.
// ---------------------------------------------------------------------------
__global__ __launch_bounds__(256) void gather1_kernel() {
    int node = blockIdx.x * 8 + (threadIdx.x >> 5);
    if (node >= NN) return;
    int lane = threadIdx.x & 31;
    int off = g_off[node], d = g_deg[node];
    float a0 = 0.f, a1 = 0.f, a2 = 0.f;
    int c0 = 0, c1 = 0, c2 = 0;
    int p = (d > 0) ? __ldg(&g_eidx[off]) : 0;
    for (int e = 0; e < d; e++) {
        int pn = (e + 1 < d) ? __ldg(&g_eidx[off + e + 1]) : 0;
        int src = p & 131071, r = p >> 17;
        float v = __ldg(&g_x1[(size_t)src * 32 + lane]);
        if (r == 0)      { a0 += v; c0++; }
        else if (r == 1) { a1 += v; c1++; }
        else             { a2 += v; c2++; }
        p = pn;
    }
    float* o = g_agg1 + (size_t)node * 96 + lane;
    o[0]  = a0 * (1.f / max(c0, 1));
    o[32] = a1 * (1.f / max(c1, 1));
    o[64] = a2 * (1.f / max(c2, 1));
}

__global__ __launch_bounds__(256) void gather2_kernel() {
    int node = blockIdx.x * 8 + (threadIdx.x >> 5);
    if (node >= NN) return;
    int lane = threadIdx.x & 31;
    int off = g_off[node], d = g_deg[node];
    float a00 = 0.f, a01 = 0.f, a10 = 0.f, a11 = 0.f, a20 = 0.f, a21 = 0.f;
    int c0 = 0, c1 = 0, c2 = 0;
    int p = (d > 0) ? __ldg(&g_eidx[off]) : 0;
    for (int e = 0; e < d; e++) {
        int pn = (e + 1 < d) ? __ldg(&g_eidx[off + e + 1]) : 0;
        int src = p & 131071, r = p >> 17;
        const float* x = g_x2 + (size_t)src * 64 + lane;
        float v0 = __ldg(x), v1 = __ldg(x + 32);
        if (r == 0)      { a00 += v0; a01 += v1; c0++; }
        else if (r == 1) { a10 += v0; a11 += v1; c1++; }
        else             { a20 += v0; a21 += v1; c2++; }
        p = pn;
    }
    float i0 = 1.f / max(c0, 1), i1 = 1.f / max(c1, 1), i2 = 1.f / max(c2, 1);
    float* o = g_agg2 + (size_t)node * 192 + lane;
    o[0]   = a00 * i0;  o[32]  = a01 * i0;
    o[64]  = a10 * i1;  o[96]  = a11 * i1;
    o[128] = a20 * i2;  o[160] = a21 * i2;
}

// ---------------------------------------------------------------------------
// GEMM: out[node] = relu([x | agg] @ [root; rel] + bias), f32x2-packed FMA.
// Block tile 128 nodes x 64 cols, 256 threads, thread tile 8m x 4c.
// Packed pairs run along K (lo=even k, hi=odd k), folded in the epilogue.
// LAYER 1 writes g_x2; LAYER 2 reduces into per-graph pool.
// ---------------------------------------------------------------------------
template <int LAYER>
__global__ __launch_bounds__(256) void gemm_kernel(const float* __restrict__ root,
                                                   const float* __restrict__ rel,
                                                   const float* __restrict__ bias,
                                                   const int* __restrict__ batch) {
    constexpr int K = (LAYER == 1) ? 128 : 256;
    constexpr int C = (LAYER == 1) ? 32 : 64;
    const float* Xm = (LAYER == 1) ? g_x1 : g_x2;
    const float* Xa = (LAYER == 1) ? g_agg1 : g_agg2;

    __shared__ __align__(16) float s_x[128 * 64];   // [m][k], pitch 64
    __shared__ __align__(16) float s_w[32 * 128];   // pair layout: [k2][c][2]

    int tid = threadIdx.x;
    int n0 = blockIdx.x * 128;
    int cg = tid & 15;          // 4-col group
    int mg = tid >> 4;          // 8-node group

    unsigned long long acc[8][4];
#pragma unroll
    for (int j = 0; j < 8; j++)
#pragma unroll
        for (int c = 0; c < 4; c++) acc[j][c] = 0ull;

    for (int kc = 0; kc < K; kc += 64) {
        // Stage X tile: 128 m x 64 k (float4 per thread x 8)
#pragma unroll
        for (int it = 0; it < 8; it++) {
            int idx = tid + it * 256;
            int m = idx >> 4, k4 = idx & 15;
            int kk = kc + k4 * 4;
            int node = n0 + m; if (node >= NN) node = NN - 1;
            const float* src = (kk < C) ? (Xm + (size_t)node * C + kk)
                                        : (Xa + (size_t)node * (3 * C) + (kk - C));
            *(float4*)(s_x + m * 64 + k4 * 4) = *(const float4*)src;
        }
        // Stage W chunk into k-pair layout: s_w[(k>>1)*128 + c*2 + (k&1)]
#pragma unroll
        for (int it = 0; it < 4; it++) {
            int idx = tid + it * 256;
            int kl = idx >> 4, c4 = idx & 15;
            int kr = kc + kl;
            const float* wsrc = (kr < C) ? (root + (size_t)kr * 64)
                                         : (rel + (size_t)(kr - C) * 64);
            float4 w = ((const float4*)wsrc)[c4];
            float* dst = s_w + (kl >> 1) * 128 + (kl & 1);
            dst[(c4 * 4 + 0) * 2] = w.x;
            dst[(c4 * 4 + 1) * 2] = w.y;
            dst[(c4 * 4 + 2) * 2] = w.z;
            dst[(c4 * 4 + 3) * 2] = w.w;
        }
        __syncthreads();

        const float* xbase = s_x + mg * 8 * 64;
        const float* wbase = s_w + cg * 8;
#pragma unroll
        for (int k4 = 0; k4 < 16; k4++) {
            // two k-pairs per step; each ull = (even-k, odd-k) operand pair
            ulonglong2 wa0 = *(const ulonglong2*)(wbase + (2 * k4 + 0) * 128);
            ulonglong2 wa1 = *(const ulonglong2*)(wbase + (2 * k4 + 0) * 128 + 4);
            ulonglong2 wb0 = *(const ulonglong2*)(wbase + (2 * k4 + 1) * 128);
            ulonglong2 wb1 = *(const ulonglong2*)(wbase + (2 * k4 + 1) * 128 + 4);
#pragma unroll
            for (int j = 0; j < 8; j++) {
                ulonglong2 xv = *(const ulonglong2*)(xbase + j * 64 + k4 * 4);
                ffma2(acc[j][0], xv.x, wa0.x);
                ffma2(acc[j][1], xv.x, wa0.y);
                ffma2(acc[j][2], xv.x, wa1.x);
                ffma2(acc[j][3], xv.x, wa1.y);
                ffma2(acc[j][0], xv.y, wb0.x);
                ffma2(acc[j][1], xv.y, wb0.y);
                ffma2(acc[j][2], xv.y, wb1.x);
                ffma2(acc[j][3], xv.y, wb1.y);
            }
        }
        __syncthreads();
    }

    float4 b = ((const float4*)bias)[cg];
#pragma unroll
    for (int j = 0; j < 8; j++) {
        int node = n0 + mg * 8 + j;
        if (node >= NN) continue;
        float2 f0 = *(float2*)&acc[j][0];
        float2 f1 = *(float2*)&acc[j][1];
        float2 f2 = *(float2*)&acc[j][2];
        float2 f3 = *(float2*)&acc[j][3];
        float4 v;
        v.x = fmaxf(f0.x + f0.y + b.x, 0.f);
        v.y = fmaxf(f1.x + f1.y + b.y, 0.f);
        v.z = fmaxf(f2.x + f2.y + b.z, 0.f);
        v.w = fmaxf(f3.x + f3.y + b.w, 0.f);
        if (LAYER == 1) {
            *(float4*)(g_x2 + (size_t)node * 64 + cg * 4) = v;
        } else {
            red_add_v4(&g_pool[batch[node] * 64 + cg * 4], v);
        }
    }
}

// ---------------------------------------------------------------------------
// Classifier; per-graph node counts via binary search on sorted batch.
// ---------------------------------------------------------------------------
static __device__ __forceinline__ int lower_bound(const int* b, int v) {
    int lo = 0, hi = NN;
    while (lo < hi) { int m = (lo + hi) >> 1; if (b[m] < v) lo = m + 1; else hi = m; }
    return lo;
}

__global__ void cls_kernel(const int* __restrict__ batch,
                           const float* __restrict__ cw,
                           const float* __restrict__ cb,
                           float* __restrict__ out) {
    int idx = blockIdx.x * blockDim.x + threadIdx.x;
    if (idx >= NG * 10) return;
    int g = idx / 10, c = idx - g * 10;
    int cnt = lower_bound(batch, g + 1) - lower_bound(batch, g);
    float inv = 1.f / max(cnt, 1);
    float acc = 0.f;
#pragma unroll
    for (int k = 0; k < 64; k++) acc = fmaf(g_pool[g * 64 + k], cw[k * 10 + c], acc);
    out[idx] = acc * inv + cb[c];
}

// ---------------------------------------------------------------------------
extern "C" void kernel_launch(void* const* d_in, const int* in_sizes, int n_in,
                              void* d_out, int out_size) {
    const int*   nf    = (const int*)d_in[0];
    const int*   ei    = (const int*)d_in[1];
    const int*   et    = (const int*)d_in[2];
    const int*   batch = (const int*)d_in[3];
    const float* se    = (const float*)d_in[4];
    const float* ce    = (const float*)d_in[5];
    const float* pw    = (const float*)d_in[6];
    const float* pb    = (const float*)d_in[7];
    const float* root1 = (const float*)d_in[8];
    const float* rel1  = (const float*)d_in[9];
    const float* bias1 = (const float*)d_in[10];
    const float* root2 = (const float*)d_in[11];
    const float* rel2  = (const float*)d_in[12];
    const float* bias2 = (const float*)d_in[13];
    const float* cw    = (const float*)d_in[14];
    const float* cb    = (const float*)d_in[15];
    float* out = (float*)d_out;

    init_embed_kernel<<<12500, 256>>>(nf, se, ce, pw, pb);
    hist_kernel<<<(NE + 255) / 256, 256>>>(ei);
    scan_a_kernel<<<98, 1024>>>();
    scan_b_kernel<<<98, 1024>>>();
    fill_kernel<<<(NE + 255) / 256, 256>>>(ei, et);

    gather1_kernel<<<(NN + 7) / 8, 256>>>();
    gemm_kernel<1><<<(NN + 127) / 128, 256>>>(root1, rel1, bias1, batch);

    gather2_kernel<<<(NN + 7) / 8, 256>>>();
    gemm_kernel<2><<<(NN + 127) / 128, 256>>>(root2, rel2, bias2, batch);

    cls_kernel<<<20, 256>>>(batch, cw, cb, out);
}

// round 3
// speedup vs baseline: 1.1866x; 1.1000x over previous
#include <cuda_runtime.h>

#define NN 100000
#define NE 1600000
#define NG 512

// ---------------------------------------------------------------------------
// Scratch (device globals; allocation is forbidden)
// ---------------------------------------------------------------------------
__device__ __align__(16) float g_x1[NN * 32];     // pre-MLP output      [NN,32]
__device__ __align__(16) float g_agg1[NN * 96];   // layer1 aggregates   [NN,3*32]
__device__ __align__(16) float g_x2[NN * 64];     // layer1 output       [NN,64]
__device__ __align__(16) float g_agg2[NN * 192];  // layer2 aggregates   [NN,3*64]
__device__ int   g_deg[NN];
__device__ int   g_off[NN];
__device__ int   g_part[128];
__device__ int   g_cursor[NN];
__device__ int   g_eidx[NE];                      // src | (rel<<17)
__device__ float g_pool[NG * 64];

static __device__ __forceinline__ void red_add_v4(float* p, float4 v) {
    asm volatile("red.global.add.v4.f32 [%0], {%1,%2,%3,%4};"
                 :: "l"(p), "f"(v.x), "f"(v.y), "f"(v.z), "f"(v.w) : "memory");
}
static __device__ __forceinline__ void ffma2(unsigned long long& d,
                                             unsigned long long a,
                                             unsigned long long b) {
    asm("fma.rn.f32x2 %0, %1, %2, %0;" : "+l"(d) : "l"(a), "l"(b));
}

// ---------------------------------------------------------------------------
// init: zero deg/pool + embedding + pre-MLP
// ---------------------------------------------------------------------------
__global__ void init_embed_kernel(const int* __restrict__ nf,
                                  const float* __restrict__ se,
                                  const float* __restrict__ ce,
                                  const float* __restrict__ pw,
                                  const float* __restrict__ pb) {
    int idx = blockIdx.x * blockDim.x + threadIdx.x;
    int stride = gridDim.x * blockDim.x;
    for (int i = idx; i < NN; i += stride) g_deg[i] = 0;
    for (int i = idx; i < NG * 64; i += stride) g_pool[i] = 0.f;
    if (idx < NN * 32) {
        int i = idx >> 5, c = idx & 31;
        int s = nf[2 * i], col = nf[2 * i + 1];
        float acc = pb[c];
#pragma unroll
        for (int k = 0; k < 8; k++) acc = fmaf(se[s * 8 + k], pw[k * 32 + c], acc);
#pragma unroll
        for (int k = 0; k < 8; k++) acc = fmaf(ce[col * 8 + k], pw[(8 + k) * 32 + c], acc);
        g_x1[(size_t)i * 32 + c] = fmaxf(acc, 0.f);
    }
}

// ---------------------------------------------------------------------------
// CSR build
// ---------------------------------------------------------------------------
__global__ void hist_kernel(const int* __restrict__ ei) {
    int e = blockIdx.x * blockDim.x + threadIdx.x;
    if (e < NE) atomicAdd(&g_deg[ei[NE + e]], 1);
}

__global__ void scan_a_kernel() {
    __shared__ int s[1024];
    int i = blockIdx.x * 1024 + threadIdx.x;
    int v = (i < NN) ? g_deg[i] : 0;
    s[threadIdx.x] = v;
    __syncthreads();
    for (int ofs = 1; ofs < 1024; ofs <<= 1) {
        int t = (threadIdx.x >= ofs) ? s[threadIdx.x - ofs] : 0;
        __syncthreads();
        s[threadIdx.x] += t;
        __syncthreads();
    }
    if (i < NN) g_off[i] = s[threadIdx.x] - v;
    if (threadIdx.x == 1023) g_part[blockIdx.x] = s[1023];
}

__global__ void scan_b_kernel() {
    __shared__ int s[1024];
    int b = blockIdx.x;
    s[threadIdx.x] = (threadIdx.x < b) ? g_part[threadIdx.x] : 0;
    __syncthreads();
    for (int ofs = 512; ofs > 0; ofs >>= 1) {
        if (threadIdx.x < ofs) s[threadIdx.x] += s[threadIdx.x + ofs];
        __syncthreads();
    }
    int prefix = s[0];
    int i = b * 1024 + threadIdx.x;
    if (i < NN) {
        int o = g_off[i] + prefix;
        g_off[i] = o;
        g_cursor[i] = o;
    }
}

__global__ void fill_kernel(const int* __restrict__ ei,
                            const int* __restrict__ et) {
    int e = blockIdx.x * blockDim.x + threadIdx.x;
    if (e >= NE) return;
    int dst = ei[NE + e];
    int pos = atomicAdd(&g_cursor[dst], 1);
    g_eidx[pos] = ei[e] | (et[e] << 17);
}

// ---------------------------------------------------------------------------
// Gathers: one warp per dst node, 4-edge software pipeline for MLP.
// ---------------------------------------------------------------------------
#define ACC1(p, v) { int r = (p) >> 17; \
    if (r == 0) { a0 += (v); c0++; } \
    else if (r == 1) { a1 += (v); c1++; } \
    else { a2 += (v); c2++; } }

__global__ __launch_bounds__(256) void gather1_kernel() {
    int node = blockIdx.x * 8 + (threadIdx.x >> 5);
    if (node >= NN) return;
    int lane = threadIdx.x & 31;
    const int* ep = g_eidx + g_off[node];
    int d = g_deg[node];
    float a0 = 0.f, a1 = 0.f, a2 = 0.f;
    int c0 = 0, c1 = 0, c2 = 0;

    int p0, p1, p2, p3;
    if (d >= 4) { p0 = __ldg(ep); p1 = __ldg(ep + 1); p2 = __ldg(ep + 2); p3 = __ldg(ep + 3); }
    int i = 0;
    while (i + 4 <= d) {
        float v0 = __ldg(&g_x1[(size_t)(p0 & 131071) * 32 + lane]);
        float v1 = __ldg(&g_x1[(size_t)(p1 & 131071) * 32 + lane]);
        float v2 = __ldg(&g_x1[(size_t)(p2 & 131071) * 32 + lane]);
        float v3 = __ldg(&g_x1[(size_t)(p3 & 131071) * 32 + lane]);
        int n0 = 0, n1 = 0, n2 = 0, n3 = 0;
        if (i + 8 <= d) {
            n0 = __ldg(ep + i + 4); n1 = __ldg(ep + i + 5);
            n2 = __ldg(ep + i + 6); n3 = __ldg(ep + i + 7);
        }
        ACC1(p0, v0); ACC1(p1, v1); ACC1(p2, v2); ACC1(p3, v3);
        p0 = n0; p1 = n1; p2 = n2; p3 = n3;
        i += 4;
    }
    for (; i < d; i++) {
        int p = __ldg(ep + i);
        float v = __ldg(&g_x1[(size_t)(p & 131071) * 32 + lane]);
        ACC1(p, v);
    }
    float* o = g_agg1 + (size_t)node * 96 + lane;
    o[0]  = a0 * (1.f / max(c0, 1));
    o[32] = a1 * (1.f / max(c1, 1));
    o[64] = a2 * (1.f / max(c2, 1));
}

#define ACC2(p, v, w) { int r = (p) >> 17; \
    if (r == 0) { a00 += (v); a01 += (w); c0++; } \
    else if (r == 1) { a10 += (v); a11 += (w); c1++; } \
    else { a20 += (v); a21 += (w); c2++; } }

__global__ __launch_bounds__(256) void gather2_kernel() {
    int node = blockIdx.x * 8 + (threadIdx.x >> 5);
    if (node >= NN) return;
    int lane = threadIdx.x & 31;
    const int* ep = g_eidx + g_off[node];
    int d = g_deg[node];
    float a00 = 0.f, a01 = 0.f, a10 = 0.f, a11 = 0.f, a20 = 0.f, a21 = 0.f;
    int c0 = 0, c1 = 0, c2 = 0;

    int p0, p1, p2, p3;
    if (d >= 4) { p0 = __ldg(ep); p1 = __ldg(ep + 1); p2 = __ldg(ep + 2); p3 = __ldg(ep + 3); }
    int i = 0;
    while (i + 4 <= d) {
        const float* x0 = g_x2 + (size_t)(p0 & 131071) * 64 + lane;
        const float* x1p = g_x2 + (size_t)(p1 & 131071) * 64 + lane;
        const float* x2p = g_x2 + (size_t)(p2 & 131071) * 64 + lane;
        const float* x3p = g_x2 + (size_t)(p3 & 131071) * 64 + lane;
        float v0 = __ldg(x0),  w0 = __ldg(x0 + 32);
        float v1 = __ldg(x1p), w1 = __ldg(x1p + 32);
        float v2 = __ldg(x2p), w2 = __ldg(x2p + 32);
        float v3 = __ldg(x3p), w3 = __ldg(x3p + 32);
        int n0 = 0, n1 = 0, n2 = 0, n3 = 0;
        if (i + 8 <= d) {
            n0 = __ldg(ep + i + 4); n1 = __ldg(ep + i + 5);
            n2 = __ldg(ep + i + 6); n3 = __ldg(ep + i + 7);
        }
        ACC2(p0, v0, w0); ACC2(p1, v1, w1); ACC2(p2, v2, w2); ACC2(p3, v3, w3);
        p0 = n0; p1 = n1; p2 = n2; p3 = n3;
        i += 4;
    }
    for (; i < d; i++) {
        int p = __ldg(ep + i);
        const float* x = g_x2 + (size_t)(p & 131071) * 64 + lane;
        float v = __ldg(x), w = __ldg(x + 32);
        ACC2(p, v, w);
    }
    float i0 = 1.f / max(c0, 1), i1 = 1.f / max(c1, 1), i2 = 1.f / max(c2, 1);
    float* o = g_agg2 + (size_t)node * 192 + lane;
    o[0]   = a00 * i0;  o[32]  = a01 * i0;
    o[64]  = a10 * i1;  o[96]  = a11 * i1;
    o[128] = a20 * i2;  o[160] = a21 * i2;
}

// ---------------------------------------------------------------------------
// GEMM: tile 256m x 64c, 256 threads, thread tile 8m x 8c, K-chunk 32,
// f32x2 packed along K. Conflict-free smem:
//   s_x: [m][kgroup], 16B groups XOR-swizzled by (mg&3)
//   s_w: pair layout, cg stride 20 floats (banks 0,20,8,28,16,4,24,12)
// ---------------------------------------------------------------------------
template <int LAYER>
__global__ __launch_bounds__(256) void gemm_kernel(const float* __restrict__ root,
                                                   const float* __restrict__ rel,
                                                   const float* __restrict__ bias,
                                                   const int* __restrict__ batch) {
    constexpr int K = (LAYER == 1) ? 128 : 256;
    constexpr int C = (LAYER == 1) ? 32 : 64;
    const float* Xm = (LAYER == 1) ? g_x1 : g_x2;
    const float* Xa = (LAYER == 1) ? g_agg1 : g_agg2;

    __shared__ __align__(16) float s_x[256 * 32];        // 32 KB
    __shared__ __align__(16) float s_w[16 * 8 * 20];     // 10 KB

    int tid = threadIdx.x;
    int n0 = blockIdx.x * 256;
    int cg = tid & 7;            // 8-col group
    int mg = tid >> 3;           // 8-row group (0..31)
    int swz = mg & 3;

    unsigned long long acc[8][8];
#pragma unroll
    for (int j = 0; j < 8; j++)
#pragma unroll
        for (int c = 0; c < 8; c++) acc[j][c] = 0ull;

    for (int kc = 0; kc < K; kc += 32) {
        // Stage X: 256 rows x 32 k
#pragma unroll
        for (int it = 0; it < 8; it++) {
            int q = tid + it * 256;
            int m = q >> 3, g = q & 7;
            int kk = kc + g * 4;
            int node = n0 + m; if (node >= NN) node = NN - 1;
            const float* src = (kk < C) ? (Xm + (size_t)node * C + kk)
                                        : (Xa + (size_t)node * (3 * C) + (kk - C));
            *(float4*)(s_x + m * 32 + ((g ^ ((m >> 3) & 3)) << 2)) = *(const float4*)src;
        }
        // Stage W: rows kc..kc+31 of [root; rel] into padded pair layout
#pragma unroll
        for (int it = 0; it < 2; it++) {
            int q = tid + it * 256;
            int kr = q >> 4, c4 = q & 15;
            int krg = kc + kr;
            const float* wsrc = (krg < C) ? (root + (size_t)krg * 64)
                                          : (rel + (size_t)(krg - C) * 64);
            float4 w = ((const float4*)wsrc)[c4];
            int k2 = kr >> 1, par = kr & 1;
            int c = c4 * 4;
            s_w[(k2 * 8 + ((c + 0) >> 3)) * 20 + ((c + 0) & 7) * 2 + par] = w.x;
            s_w[(k2 * 8 + ((c + 1) >> 3)) * 20 + ((c + 1) & 7) * 2 + par] = w.y;
            s_w[(k2 * 8 + ((c + 2) >> 3)) * 20 + ((c + 2) & 7) * 2 + par] = w.z;
            s_w[(k2 * 8 + ((c + 3) >> 3)) * 20 + ((c + 3) & 7) * 2 + par] = w.w;
        }
        __syncthreads();

#pragma unroll
        for (int g = 0; g < 8; g++) {
            ulonglong2 wa[2], wb[2];
            const ulonglong2* wpA = (const ulonglong2*)(s_w + ((2 * g + 0) * 8 + cg) * 20);
            const ulonglong2* wpB = (const ulonglong2*)(s_w + ((2 * g + 1) * 8 + cg) * 20);
            wa[0] = wpA[0]; wa[1] = wpA[1];
            wb[0] = wpB[0]; wb[1] = wpB[1];
            ulonglong2 wa2[2], wb2[2];
            wa2[0] = wpA[2]; wa2[1] = wpA[3];
            wb2[0] = wpB[2]; wb2[1] = wpB[3];
#pragma unroll
            for (int j = 0; j < 8; j++) {
                ulonglong2 xv = *(const ulonglong2*)(s_x + (mg * 8 + j) * 32 + ((g ^ swz) << 2));
                ffma2(acc[j][0], xv.x, wa[0].x);
                ffma2(acc[j][1], xv.x, wa[0].y);
                ffma2(acc[j][2], xv.x, wa[1].x);
                ffma2(acc[j][3], xv.x, wa[1].y);
                ffma2(acc[j][4], xv.x, wa2[0].x);
                ffma2(acc[j][5], xv.x, wa2[0].y);
                ffma2(acc[j][6], xv.x, wa2[1].x);
                ffma2(acc[j][7], xv.x, wa2[1].y);
                ffma2(acc[j][0], xv.y, wb[0].x);
                ffma2(acc[j][1], xv.y, wb[0].y);
                ffma2(acc[j][2], xv.y, wb[1].x);
                ffma2(acc[j][3], xv.y, wb[1].y);
                ffma2(acc[j][4], xv.y, wb2[0].x);
                ffma2(acc[j][5], xv.y, wb2[0].y);
                ffma2(acc[j][6], xv.y, wb2[1].x);
                ffma2(acc[j][7], xv.y, wb2[1].y);
            }
        }
        __syncthreads();
    }

    float4 b0 = ((const float4*)bias)[cg * 2];
    float4 b1 = ((const float4*)bias)[cg * 2 + 1];
#pragma unroll
    for (int j = 0; j < 8; j++) {
        int node = n0 + mg * 8 + j;
        if (node >= NN) continue;
        float2 f[8];
#pragma unroll
        for (int c = 0; c < 8; c++) f[c] = *(float2*)&acc[j][c];
        float4 v0, v1;
        v0.x = fmaxf(f[0].x + f[0].y + b0.x, 0.f);
        v0.y = fmaxf(f[1].x + f[1].y + b0.y, 0.f);
        v0.z = fmaxf(f[2].x + f[2].y + b0.z, 0.f);
        v0.w = fmaxf(f[3].x + f[3].y + b0.w, 0.f);
        v1.x = fmaxf(f[4].x + f[4].y + b1.x, 0.f);
        v1.y = fmaxf(f[5].x + f[5].y + b1.y, 0.f);
        v1.z = fmaxf(f[6].x + f[6].y + b1.z, 0.f);
        v1.w = fmaxf(f[7].x + f[7].y + b1.w, 0.f);
        if (LAYER == 1) {
            *(float4*)(g_x2 + (size_t)node * 64 + cg * 8)     = v0;
            *(float4*)(g_x2 + (size_t)node * 64 + cg * 8 + 4) = v1;
        } else {
            int g = batch[node];
            red_add_v4(&g_pool[g * 64 + cg * 8], v0);
            red_add_v4(&g_pool[g * 64 + cg * 8 + 4], v1);
        }
    }
}

// ---------------------------------------------------------------------------
// Classifier (graph counts via binary search on sorted batch)
// ---------------------------------------------------------------------------
static __device__ __forceinline__ int lower_bound(const int* b, int v) {
    int lo = 0, hi = NN;
    while (lo < hi) { int m = (lo + hi) >> 1; if (b[m] < v) lo = m + 1; else hi = m; }
    return lo;
}

__global__ void cls_kernel(const int* __restrict__ batch,
                           const float* __restrict__ cw,
                           const float* __restrict__ cb,
                           float* __restrict__ out) {
    int idx = blockIdx.x * blockDim.x + threadIdx.x;
    if (idx >= NG * 10) return;
    int g = idx / 10, c = idx - g * 10;
    int cnt = lower_bound(batch, g + 1) - lower_bound(batch, g);
    float inv = 1.f / max(cnt, 1);
    float acc = 0.f;
#pragma unroll
    for (int k = 0; k < 64; k++) acc = fmaf(g_pool[g * 64 + k], cw[k * 10 + c], acc);
    out[idx] = acc * inv + cb[c];
}

// ---------------------------------------------------------------------------
extern "C" void kernel_launch(void* const* d_in, const int* in_sizes, int n_in,
                              void* d_out, int out_size) {
    const int*   nf    = (const int*)d_in[0];
    const int*   ei    = (const int*)d_in[1];
    const int*   et    = (const int*)d_in[2];
    const int*   batch = (const int*)d_in[3];
    const float* se    = (const float*)d_in[4];
    const float* ce    = (const float*)d_in[5];
    const float* pw    = (const float*)d_in[6];
    const float* pb    = (const float*)d_in[7];
    const float* root1 = (const float*)d_in[8];
    const float* rel1  = (const float*)d_in[9];
    const float* bias1 = (const float*)d_in[10];
    const float* root2 = (const float*)d_in[11];
    const float* rel2  = (const float*)d_in[12];
    const float* bias2 = (const float*)d_in[13];
    const float* cw    = (const float*)d_in[14];
    const float* cb    = (const float*)d_in[15];
    float* out = (float*)d_out;

    init_embed_kernel<<<12500, 256>>>(nf, se, ce, pw, pb);
    hist_kernel<<<(NE + 255) / 256, 256>>>(ei);
    scan_a_kernel<<<98, 1024>>>();
    scan_b_kernel<<<98, 1024>>>();
    fill_kernel<<<(NE + 255) / 256, 256>>>(ei, et);

    gather1_kernel<<<(NN + 7) / 8, 256>>>();
    gemm_kernel<1><<<(NN + 255) / 256, 256>>>(root1, rel1, bias1, batch);

    gather2_kernel<<<(NN + 7) / 8, 256>>>();
    gemm_kernel<2><<<(NN + 255) / 256, 256>>>(root2, rel2, bias2, batch);

    cls_kernel<<<20, 256>>>(batch, cw, cb, out);
}

// round 4
// speedup vs baseline: 1.2635x; 1.0648x over previous
#include <cuda_runtime.h>

#define NN 100000
#define NE 1600000
#define NG 512

// ---------------------------------------------------------------------------
// Scratch (device globals; allocation is forbidden)
// ---------------------------------------------------------------------------
__device__ __align__(16) float g_x1[NN * 32];     // pre-MLP output      [NN,32]
__device__ __align__(16) float g_agg1[NN * 96];   // layer1 aggregates   [NN,3*32]
__device__ __align__(16) float g_x2[NN * 64];     // layer1 output       [NN,64]
__device__ __align__(16) float g_agg2[NN * 192];  // layer2 aggregates   [NN,3*64]
__device__ int   g_deg[NN];
__device__ int   g_off[NN];
__device__ int   g_part[128];
__device__ int   g_cursor[NN];
__device__ int   g_eidx[NE];                      // src | (rel<<17)
__device__ float g_pool[NG * 64];

static __device__ __forceinline__ void red_add_v4(float* p, float4 v) {
    asm volatile("red.global.add.v4.f32 [%0], {%1,%2,%3,%4};"
                 :: "l"(p), "f"(v.x), "f"(v.y), "f"(v.z), "f"(v.w) : "memory");
}
static __device__ __forceinline__ void ffma2(unsigned long long& d,
                                             unsigned long long a,
                                             unsigned long long b) {
    asm("fma.rn.f32x2 %0, %1, %2, %0;" : "+l"(d) : "l"(a), "l"(b));
}
static __device__ __forceinline__ void f4add(float4& a, float4 b) {
    a.x += b.x; a.y += b.y; a.z += b.z; a.w += b.w;
}
static __device__ __forceinline__ float4 f4scale(float4 a, float s) {
    return make_float4(a.x * s, a.y * s, a.z * s, a.w * s);
}

// ---------------------------------------------------------------------------
// init: zero deg/pool + embedding + pre-MLP
// ---------------------------------------------------------------------------
__global__ void init_embed_kernel(const int* __restrict__ nf,
                                  const float* __restrict__ se,
                                  const float* __restrict__ ce,
                                  const float* __restrict__ pw,
                                  const float* __restrict__ pb) {
    int idx = blockIdx.x * blockDim.x + threadIdx.x;
    int stride = gridDim.x * blockDim.x;
    for (int i = idx; i < NN; i += stride) g_deg[i] = 0;
    for (int i = idx; i < NG * 64; i += stride) g_pool[i] = 0.f;
    if (idx < NN * 32) {
        int i = idx >> 5, c = idx & 31;
        int s = nf[2 * i], col = nf[2 * i + 1];
        float acc = pb[c];
#pragma unroll
        for (int k = 0; k < 8; k++) acc = fmaf(se[s * 8 + k], pw[k * 32 + c], acc);
#pragma unroll
        for (int k = 0; k < 8; k++) acc = fmaf(ce[col * 8 + k], pw[(8 + k) * 32 + c], acc);
        g_x1[(size_t)i * 32 + c] = fmaxf(acc, 0.f);
    }
}

// ---------------------------------------------------------------------------
// CSR build
// ---------------------------------------------------------------------------
__global__ void hist_kernel(const int* __restrict__ ei) {
    int e = blockIdx.x * blockDim.x + threadIdx.x;
    if (e < NE) atomicAdd(&g_deg[ei[NE + e]], 1);
}

__global__ void scan_a_kernel() {
    __shared__ int s[1024];
    int i = blockIdx.x * 1024 + threadIdx.x;
    int v = (i < NN) ? g_deg[i] : 0;
    s[threadIdx.x] = v;
    __syncthreads();
    for (int ofs = 1; ofs < 1024; ofs <<= 1) {
        int t = (threadIdx.x >= ofs) ? s[threadIdx.x - ofs] : 0;
        __syncthreads();
        s[threadIdx.x] += t;
        __syncthreads();
    }
    if (i < NN) g_off[i] = s[threadIdx.x] - v;
    if (threadIdx.x == 1023) g_part[blockIdx.x] = s[1023];
}

__global__ void scan_b_kernel() {
    __shared__ int s[1024];
    int b = blockIdx.x;
    s[threadIdx.x] = (threadIdx.x < b) ? g_part[threadIdx.x] : 0;
    __syncthreads();
    for (int ofs = 512; ofs > 0; ofs >>= 1) {
        if (threadIdx.x < ofs) s[threadIdx.x] += s[threadIdx.x + ofs];
        __syncthreads();
    }
    int prefix = s[0];
    int i = b * 1024 + threadIdx.x;
    if (i < NN) {
        int o = g_off[i] + prefix;
        g_off[i] = o;
        g_cursor[i] = o;
    }
}

__global__ void fill_kernel(const int* __restrict__ ei,
                            const int* __restrict__ et) {
    int e = blockIdx.x * blockDim.x + threadIdx.x;
    if (e >= NE) return;
    int dst = ei[NE + e];
    int pos = atomicAdd(&g_cursor[dst], 1);
    g_eidx[pos] = ei[e] | (et[e] << 17);
}

// ---------------------------------------------------------------------------
// gather1: 4 nodes per warp (8 lanes each, float4 cols), 2-edge unroll.
// ---------------------------------------------------------------------------
__global__ __launch_bounds__(256) void gather1_kernel() {
    int warp = blockIdx.x * 8 + (threadIdx.x >> 5);
    int lane = threadIdx.x & 31;
    int grp = lane >> 3, sub = lane & 7;
    int node = warp * 4 + grp;
    bool valid = node < NN;
    int off = valid ? g_off[node] : 0;
    int d   = valid ? g_deg[node] : 0;
    const int* ep = g_eidx + off;

    int dmax = d;
    dmax = max(dmax, __shfl_xor_sync(0xffffffffu, dmax, 8));
    dmax = max(dmax, __shfl_xor_sync(0xffffffffu, dmax, 16));

    float4 a0 = {0,0,0,0}, a1 = a0, a2 = a0;
    int c0 = 0, c1 = 0, c2 = 0;

    int pA = 0, pB = 0;
    if (0 < d) pA = __ldg(ep);
    if (1 < d) pB = __ldg(ep + 1);
    int i = 0;
    for (; i + 2 <= dmax; i += 2) {
        float4 vA = {0,0,0,0}, vB = {0,0,0,0};
        int rA = (i < d) ? (pA >> 17) : 3;
        int rB = (i + 1 < d) ? (pB >> 17) : 3;
        if (i < d)     vA = *(const float4*)(g_x1 + (size_t)(pA & 131071) * 32 + sub * 4);
        if (i + 1 < d) vB = *(const float4*)(g_x1 + (size_t)(pB & 131071) * 32 + sub * 4);
        int pC = 0, pD = 0;
        if (i + 2 < d) pC = __ldg(ep + i + 2);
        if (i + 3 < d) pD = __ldg(ep + i + 3);
        if (rA == 0)      { f4add(a0, vA); c0++; }
        else if (rA == 1) { f4add(a1, vA); c1++; }
        else if (rA == 2) { f4add(a2, vA); c2++; }
        if (rB == 0)      { f4add(a0, vB); c0++; }
        else if (rB == 1) { f4add(a1, vB); c1++; }
        else if (rB == 2) { f4add(a2, vB); c2++; }
        pA = pC; pB = pD;
    }
    if (i < dmax && i < d) {
        int r = pA >> 17;
        float4 v = *(const float4*)(g_x1 + (size_t)(pA & 131071) * 32 + sub * 4);
        if (r == 0)      { f4add(a0, v); c0++; }
        else if (r == 1) { f4add(a1, v); c1++; }
        else             { f4add(a2, v); c2++; }
    }
    if (valid) {
        float* o = g_agg1 + (size_t)node * 96 + sub * 4;
        *(float4*)(o)      = f4scale(a0, 1.f / max(c0, 1));
        *(float4*)(o + 32) = f4scale(a1, 1.f / max(c1, 1));
        *(float4*)(o + 64) = f4scale(a2, 1.f / max(c2, 1));
    }
}

// ---------------------------------------------------------------------------
// gather2: 2 nodes per warp (16 lanes each, float4 cols), 2-edge unroll.
// ---------------------------------------------------------------------------
__global__ __launch_bounds__(256) void gather2_kernel() {
    int warp = blockIdx.x * 8 + (threadIdx.x >> 5);
    int lane = threadIdx.x & 31;
    int grp = lane >> 4, sub = lane & 15;
    int node = warp * 2 + grp;
    bool valid = node < NN;
    int off = valid ? g_off[node] : 0;
    int d   = valid ? g_deg[node] : 0;
    const int* ep = g_eidx + off;

    int dmax = max(d, __shfl_xor_sync(0xffffffffu, d, 16));

    float4 a0 = {0,0,0,0}, a1 = a0, a2 = a0;
    int c0 = 0, c1 = 0, c2 = 0;

    int pA = 0, pB = 0;
    if (0 < d) pA = __ldg(ep);
    if (1 < d) pB = __ldg(ep + 1);
    int i = 0;
    for (; i + 2 <= dmax; i += 2) {
        float4 vA = {0,0,0,0}, vB = {0,0,0,0};
        int rA = (i < d) ? (pA >> 17) : 3;
        int rB = (i + 1 < d) ? (pB >> 17) : 3;
        if (i < d)     vA = *(const float4*)(g_x2 + (size_t)(pA & 131071) * 64 + sub * 4);
        if (i + 1 < d) vB = *(const float4*)(g_x2 + (size_t)(pB & 131071) * 64 + sub * 4);
        int pC = 0, pD = 0;
        if (i + 2 < d) pC = __ldg(ep + i + 2);
        if (i + 3 < d) pD = __ldg(ep + i + 3);
        if (rA == 0)      { f4add(a0, vA); c0++; }
        else if (rA == 1) { f4add(a1, vA); c1++; }
        else if (rA == 2) { f4add(a2, vA); c2++; }
        if (rB == 0)      { f4add(a0, vB); c0++; }
        else if (rB == 1) { f4add(a1, vB); c1++; }
        else if (rB == 2) { f4add(a2, vB); c2++; }
        pA = pC; pB = pD;
    }
    if (i < dmax && i < d) {
        int r = pA >> 17;
        float4 v = *(const float4*)(g_x2 + (size_t)(pA & 131071) * 64 + sub * 4);
        if (r == 0)      { f4add(a0, v); c0++; }
        else if (r == 1) { f4add(a1, v); c1++; }
        else             { f4add(a2, v); c2++; }
    }
    if (valid) {
        float* o = g_agg2 + (size_t)node * 192 + sub * 4;
        *(float4*)(o)       = f4scale(a0, 1.f / max(c0, 1));
        *(float4*)(o + 64)  = f4scale(a1, 1.f / max(c1, 1));
        *(float4*)(o + 128) = f4scale(a2, 1.f / max(c2, 1));
    }
}

// ---------------------------------------------------------------------------
// GEMM: tile 128m x 64c, 256 threads, thread tile 4m x 8c, K-chunk 32,
// f32x2 packed along K, 2 blocks/SM.
// ---------------------------------------------------------------------------
template <int LAYER>
__global__ __launch_bounds__(256, 2) void gemm_kernel(const float* __restrict__ root,
                                                      const float* __restrict__ rel,
                                                      const float* __restrict__ bias,
                                                      const int* __restrict__ batch) {
    constexpr int K = (LAYER == 1) ? 128 : 256;
    constexpr int C = (LAYER == 1) ? 32 : 64;
    const float* Xm = (LAYER == 1) ? g_x1 : g_x2;
    const float* Xa = (LAYER == 1) ? g_agg1 : g_agg2;

    __shared__ __align__(16) float s_x[128 * 32];        // 16 KB
    __shared__ __align__(16) float s_w[16 * 8 * 20];     // 10 KB

    int tid = threadIdx.x;
    int n0 = blockIdx.x * 128;
    int cg = tid & 7;            // 8-col group
    int mg = tid >> 3;           // 4-row group (0..31)
    int swz = mg & 3;

    unsigned long long acc[4][8];
#pragma unroll
    for (int j = 0; j < 4; j++)
#pragma unroll
        for (int c = 0; c < 8; c++) acc[j][c] = 0ull;

    for (int kc = 0; kc < K; kc += 32) {
        // Stage X: 128 rows x 32 k
#pragma unroll
        for (int it = 0; it < 4; it++) {
            int q = tid + it * 256;
            int m = q >> 3, g = q & 7;
            int kk = kc + g * 4;
            int node = n0 + m; if (node >= NN) node = NN - 1;
            const float* src = (kk < C) ? (Xm + (size_t)node * C + kk)
                                        : (Xa + (size_t)node * (3 * C) + (kk - C));
            *(float4*)(s_x + m * 32 + ((g ^ ((m >> 2) & 3)) << 2)) = *(const float4*)src;
        }
        // Stage W: rows kc..kc+31 of [root; rel] into padded pair layout
#pragma unroll
        for (int it = 0; it < 2; it++) {
            int q = tid + it * 256;
            int kr = q >> 4, c4 = q & 15;
            int krg = kc + kr;
            const float* wsrc = (krg < C) ? (root + (size_t)krg * 64)
                                          : (rel + (size_t)(krg - C) * 64);
            float4 w = ((const float4*)wsrc)[c4];
            int k2 = kr >> 1, par = kr & 1;
            int c = c4 * 4;
            s_w[(k2 * 8 + ((c + 0) >> 3)) * 20 + ((c + 0) & 7) * 2 + par] = w.x;
            s_w[(k2 * 8 + ((c + 1) >> 3)) * 20 + ((c + 1) & 7) * 2 + par] = w.y;
            s_w[(k2 * 8 + ((c + 2) >> 3)) * 20 + ((c + 2) & 7) * 2 + par] = w.z;
            s_w[(k2 * 8 + ((c + 3) >> 3)) * 20 + ((c + 3) & 7) * 2 + par] = w.w;
        }
        __syncthreads();

#pragma unroll
        for (int g = 0; g < 8; g++) {
            const ulonglong2* wpA = (const ulonglong2*)(s_w + ((2 * g + 0) * 8 + cg) * 20);
            const ulonglong2* wpB = (const ulonglong2*)(s_w + ((2 * g + 1) * 8 + cg) * 20);
            ulonglong2 wa0 = wpA[0], wa1 = wpA[1], wa2 = wpA[2], wa3 = wpA[3];
            ulonglong2 wb0 = wpB[0], wb1 = wpB[1], wb2 = wpB[2], wb3 = wpB[3];
#pragma unroll
            for (int j = 0; j < 4; j++) {
                ulonglong2 xv = *(const ulonglong2*)(s_x + (mg * 4 + j) * 32 + ((g ^ swz) << 2));
                ffma2(acc[j][0], xv.x, wa0.x);
                ffma2(acc[j][1], xv.x, wa0.y);
                ffma2(acc[j][2], xv.x, wa1.x);
                ffma2(acc[j][3], xv.x, wa1.y);
                ffma2(acc[j][4], xv.x, wa2.x);
                ffma2(acc[j][5], xv.x, wa2.y);
                ffma2(acc[j][6], xv.x, wa3.x);
                ffma2(acc[j][7], xv.x, wa3.y);
                ffma2(acc[j][0], xv.y, wb0.x);
                ffma2(acc[j][1], xv.y, wb0.y);
                ffma2(acc[j][2], xv.y, wb1.x);
                ffma2(acc[j][3], xv.y, wb1.y);
                ffma2(acc[j][4], xv.y, wb2.x);
                ffma2(acc[j][5], xv.y, wb2.y);
                ffma2(acc[j][6], xv.y, wb3.x);
                ffma2(acc[j][7], xv.y, wb3.y);
            }
        }
        __syncthreads();
    }

    float4 b0 = ((const float4*)bias)[cg * 2];
    float4 b1 = ((const float4*)bias)[cg * 2 + 1];
#pragma unroll
    for (int j = 0; j < 4; j++) {
        int node = n0 + mg * 4 + j;
        if (node >= NN) continue;
        float2 f[8];
#pragma unroll
        for (int c = 0; c < 8; c++) f[c] = *(float2*)&acc[j][c];
        float4 v0, v1;
        v0.x = fmaxf(f[0].x + f[0].y + b0.x, 0.f);
        v0.y = fmaxf(f[1].x + f[1].y + b0.y, 0.f);
        v0.z = fmaxf(f[2].x + f[2].y + b0.z, 0.f);
        v0.w = fmaxf(f[3].x + f[3].y + b0.w, 0.f);
        v1.x = fmaxf(f[4].x + f[4].y + b1.x, 0.f);
        v1.y = fmaxf(f[5].x + f[5].y + b1.y, 0.f);
        v1.z = fmaxf(f[6].x + f[6].y + b1.z, 0.f);
        v1.w = fmaxf(f[7].x + f[7].y + b1.w, 0.f);
        if (LAYER == 1) {
            *(float4*)(g_x2 + (size_t)node * 64 + cg * 8)     = v0;
            *(float4*)(g_x2 + (size_t)node * 64 + cg * 8 + 4) = v1;
        } else {
            int g = batch[node];
            red_add_v4(&g_pool[g * 64 + cg * 8], v0);
            red_add_v4(&g_pool[g * 64 + cg * 8 + 4], v1);
        }
    }
}

// ---------------------------------------------------------------------------
// Classifier (graph counts via binary search on sorted batch)
// ---------------------------------------------------------------------------
static __device__ __forceinline__ int lower_bound(const int* b, int v) {
    int lo = 0, hi = NN;
    while (lo < hi) { int m = (lo + hi) >> 1; if (b[m] < v) lo = m + 1; else hi = m; }
    return lo;
}

__global__ void cls_kernel(const int* __restrict__ batch,
                           const float* __restrict__ cw,
                           const float* __restrict__ cb,
                           float* __restrict__ out) {
    int idx = blockIdx.x * blockDim.x + threadIdx.x;
    if (idx >= NG * 10) return;
    int g = idx / 10, c = idx - g * 10;
    int cnt = lower_bound(batch, g + 1) - lower_bound(batch, g);
    float inv = 1.f / max(cnt, 1);
    float acc = 0.f;
#pragma unroll
    for (int k = 0; k < 64; k++) acc = fmaf(g_pool[g * 64 + k], cw[k * 10 + c], acc);
    out[idx] = acc * inv + cb[c];
}

// ---------------------------------------------------------------------------
extern "C" void kernel_launch(void* const* d_in, const int* in_sizes, int n_in,
                              void* d_out, int out_size) {
    const int*   nf    = (const int*)d_in[0];
    const int*   ei    = (const int*)d_in[1];
    const int*   et    = (const int*)d_in[2];
    const int*   batch = (const int*)d_in[3];
    const float* se    = (const float*)d_in[4];
    const float* ce    = (const float*)d_in[5];
    const float* pw    = (const float*)d_in[6];
    const float* pb    = (const float*)d_in[7];
    const float* root1 = (const float*)d_in[8];
    const float* rel1  = (const float*)d_in[9];
    const float* bias1 = (const float*)d_in[10];
    const float* root2 = (const float*)d_in[11];
    const float* rel2  = (const float*)d_in[12];
    const float* bias2 = (const float*)d_in[13];
    const float* cw    = (const float*)d_in[14];
    const float* cb    = (const float*)d_in[15];
    float* out = (float*)d_out;

    init_embed_kernel<<<12500, 256>>>(nf, se, ce, pw, pb);
    hist_kernel<<<(NE + 255) / 256, 256>>>(ei);
    scan_a_kernel<<<98, 1024>>>();
    scan_b_kernel<<<98, 1024>>>();
    fill_kernel<<<(NE + 255) / 256, 256>>>(ei, et);

    gather1_kernel<<<(NN + 31) / 32, 256>>>();
    gemm_kernel<1><<<(NN + 127) / 128, 256>>>(root1, rel1, bias1, batch);

    gather2_kernel<<<(NN + 15) / 16, 256>>>();
    gemm_kernel<2><<<(NN + 127) / 128, 256>>>(root2, rel2, bias2, batch);

    cls_kernel<<<20, 256>>>(batch, cw, cb, out);
}